// round 7
// baseline (speedup 1.0000x reference)
#include <cuda_runtime.h>
#include <cuda_fp16.h>
#include <cstdint>

#define NNODES 50000
#define FDIM   256
#define KMIX   5
#define EMAX   1700000

// ---------------- scratch ----------------
__device__ unsigned g_mbits[NNODES * 8];      // bit mask, 256 bits/node
__device__ float g_indeg[NNODES];
__device__ float g_gamma[NNODES * KMIX];
__device__ int   g_flags[2];
__device__ int   g_count[NNODES];
__device__ int   g_cursor[NNODES];
__device__ int   g_offset[NNODES + 1];
__device__ int   g_sorted[EMAX];
__device__ float g_ivar[KMIX * FDIM];         // exp(-logvars), precomputed once
__device__ __half g_S0h[NNODES * FDIM];       // fp16 hi of aggregated S0
__device__ __half g_S0l[NNODES * FDIM];       // fp16 lo residual
__device__ __half g_SMh[NNODES * FDIM];       // aggregated mask counts (exact fp16)
// B concat (single fp16): [group g (32 outs)][352 rows (n)][256 (k)]
__device__ __half g_B[8][352 * 256];

// ---------------- PTX helpers (baseline ISA only) ----------------
__device__ __forceinline__ uint32_t smem_u32(const void* p) {
    uint32_t a;
    asm("{ .reg .u64 t; cvta.to.shared.u64 t, %1; cvt.u32.u64 %0, t; }" : "=r"(a) : "l"(p));
    return a;
}
__device__ __forceinline__ void cpasync16(uint32_t dst, const void* src) {
    asm volatile("cp.async.cg.shared.global [%0], [%1], 16;" :: "r"(dst), "l"(src));
}
#define CP_COMMIT() asm volatile("cp.async.commit_group;" ::: "memory")
#define CP_WAIT1()  asm volatile("cp.async.wait_group 1;" ::: "memory")
#define CP_WAIT0()  asm volatile("cp.async.wait_group 0;" ::: "memory")

__device__ __forceinline__ void ldsm4(uint32_t* r, uint32_t addr) {
    asm volatile("ldmatrix.sync.aligned.m8n8.x4.shared.b16 {%0,%1,%2,%3}, [%4];"
                 : "=r"(r[0]), "=r"(r[1]), "=r"(r[2]), "=r"(r[3]) : "r"(addr));
}
__device__ __forceinline__ void mma16816(float* d, const uint32_t* a, const uint32_t* b) {
    asm volatile("mma.sync.aligned.m16n8k16.row.col.f32.f16.f16.f32 "
                 "{%0,%1,%2,%3}, {%4,%5,%6,%7}, {%8,%9}, {%0,%1,%2,%3};"
                 : "+f"(d[0]), "+f"(d[1]), "+f"(d[2]), "+f"(d[3])
                 : "r"(a[0]), "r"(a[1]), "r"(a[2]), "r"(a[3]), "r"(b[0]), "r"(b[1]));
}

// ---------------- dtype detection + zero counters ----------------
__global__ void detect_kernel(const void* mask, const void* edges) {
    int t = threadIdx.x;
    int any_m = 0, any_e = 0;
    const unsigned char* mb = (const unsigned char*)mask;
    const int* ei = (const int*)edges;
    for (int i = t; i < 4096; i += 256) {
        if (mb[4 * i + 1] != 0) any_m = 1;
        if (ei[2 * i + 1] != 0) any_e = 1;
    }
    any_m = __syncthreads_or(any_m);
    any_e = __syncthreads_or(any_e);
    if (t == 0) { g_flags[0] = any_m ? 1 : 0; g_flags[1] = any_e ? 0 : 1; }
}

__global__ void zero_kernel() {
    int i = blockIdx.x * blockDim.x + threadIdx.x;
    if (i < NNODES) { g_count[i] = 0; g_cursor[i] = 0; }
}

// ---------------- ivar precompute (1280 values, once) ----------------
__global__ void ivar_kernel(const float* __restrict__ logvars) {
    int i = blockIdx.x * blockDim.x + threadIdx.x;
    if (i < KMIX * FDIM) g_ivar[i] = expf(-logvars[i]);
}

// ---------------- prep: mbits + gamma ----------------
__global__ __launch_bounds__(256) void prep_kernel(
    const float* __restrict__ x, const void* __restrict__ mask,
    const float* __restrict__ logp, const float* __restrict__ means)
{
    int n = blockIdx.x;
    int f = threadIdx.x;
    int idx = n * FDIM + f;
    int m = g_flags[0] ? (int)((const unsigned char*)mask)[idx]
                       : ((const int*)mask)[idx];
    float xv = x[idx];

    unsigned bal = __ballot_sync(0xffffffffu, m);
    int w = f >> 5, lane = f & 31;
    if (lane == 0) g_mbits[n * 8 + w] = bal;

    float q[KMIX];
#pragma unroll
    for (int k = 0; k < KMIX; k++) {
        float d = xv - means[k * FDIM + f];
        float iv = g_ivar[k * FDIM + f];
        q[k] = m ? 0.0f : d * d * iv;
    }
#pragma unroll
    for (int k = 0; k < KMIX; k++)
        for (int off = 16; off; off >>= 1)
            q[k] += __shfl_down_sync(0xffffffffu, q[k], off);

    __shared__ float red[8][KMIX];
    if (lane == 0)
#pragma unroll
        for (int k = 0; k < KMIX; k++) red[w][k] = q[k];
    __syncthreads();
    if (f == 0) {
        float l[KMIX], mx = -1e30f;
#pragma unroll
        for (int k = 0; k < KMIX; k++) {
            float s = 0.f;
            for (int ww = 0; ww < 8; ww++) s += red[ww][k];
            l[k] = logp[k] - 0.5f * s;
            mx = fmaxf(mx, l[k]);
        }
        float e[KMIX], se = 0.f;
#pragma unroll
        for (int k = 0; k < KMIX; k++) { e[k] = __expf(l[k] - mx); se += e[k]; }
        float inv = 1.0f / se;
#pragma unroll
        for (int k = 0; k < KMIX; k++) g_gamma[n * KMIX + k] = e[k] * inv;
    }
}

// ---------------- CSR build ----------------
__global__ void count_kernel(const void* __restrict__ edges, int E) {
    int i = blockIdx.x * blockDim.x + threadIdx.x;
    if (i >= E) return;
    int dst = g_flags[1] ? (int)((const long long*)edges)[E + i]
                         : ((const int*)edges)[E + i];
    atomicAdd(&g_count[dst], 1);
}

__global__ __launch_bounds__(1024) void scan_kernel() {
    const int SEG = (NNODES + 1023) / 1024;
    int t = threadIdx.x;
    int base = t * SEG;
    int s = 0;
    for (int i = 0; i < SEG; i++) {
        int idx = base + i;
        if (idx < NNODES) s += g_count[idx];
    }
    __shared__ int ss[1024];
    ss[t] = s;
    __syncthreads();
    for (int off = 1; off < 1024; off <<= 1) {
        int v = (t >= off) ? ss[t - off] : 0;
        __syncthreads();
        ss[t] += v;
        __syncthreads();
    }
    int run = ss[t] - s;
    for (int i = 0; i < SEG; i++) {
        int idx = base + i;
        if (idx < NNODES) { g_offset[idx] = run; run += g_count[idx]; }
    }
    if (t == 1023) g_offset[NNODES] = ss[1023];
}

__global__ void scatter_kernel(const void* __restrict__ edges, int E) {
    int i = blockIdx.x * blockDim.x + threadIdx.x;
    if (i >= E) return;
    int src, dst;
    if (g_flags[1]) {
        const long long* e = (const long long*)edges;
        src = (int)e[i]; dst = (int)e[E + i];
    } else {
        const int* e = (const int*)edges;
        src = e[i]; dst = e[E + i];
    }
    int pos = atomicAdd(&g_cursor[dst], 1);
    g_sorted[g_offset[dst] + pos] = src;
}

// ---------------- aggregate: CSR gather -> S0h/S0l/SMh + indeg ----------
__global__ __launch_bounds__(256) void aggregate_kernel(const float* __restrict__ x) {
    int n = blockIdx.x;
    int f = threadIdx.x;
    int wsel = f >> 5, bsel = f & 31;

    int beg = g_offset[n], end = g_offset[n + 1];

    unsigned mb = g_mbits[n * 8 + wsel];
    int bit = (mb >> bsel) & 1;
    float xv = __ldg(&x[(size_t)n * FDIM + f]);
    float accS = bit ? 0.0f : xv;
    int cnt = bit;

    __shared__ int ssrc[256];
    for (int chunk = beg; chunk < end; chunk += 256) {
        int nload = min(256, end - chunk);
        __syncthreads();
        if (f < nload) ssrc[f] = g_sorted[chunk + f];
        __syncthreads();
        int i = 0;
        for (; i + 2 <= nload; i += 2) {
            int s0 = ssrc[i], s1 = ssrc[i + 1];
            unsigned m0 = __ldg(&g_mbits[s0 * 8 + wsel]);
            unsigned m1 = __ldg(&g_mbits[s1 * 8 + wsel]);
            float v0 = __ldg(&x[(size_t)s0 * FDIM + f]);
            float v1 = __ldg(&x[(size_t)s1 * FDIM + f]);
            int b0 = (m0 >> bsel) & 1, b1 = (m1 >> bsel) & 1;
            accS += b0 ? 0.0f : v0;
            accS += b1 ? 0.0f : v1;
            cnt += b0 + b1;
        }
        if (i < nload) {
            int s0 = ssrc[i];
            unsigned m0 = __ldg(&g_mbits[s0 * 8 + wsel]);
            float v0 = __ldg(&x[(size_t)s0 * FDIM + f]);
            int b0 = (m0 >> bsel) & 1;
            accS += b0 ? 0.0f : v0;
            cnt += b0;
        }
    }

    int idx = n * FDIM + f;
    __half h = __float2half_rn(accS);
    g_S0h[idx] = h;
    g_S0l[idx] = __float2half_rn(accS - __half2float(h));
    g_SMh[idx] = __float2half_rn((float)cnt);
    if (f == 0) g_indeg[n] = (float)(end - beg);
}

// ---------------- B precompute (n-concat, single fp16) ----------------
__global__ __launch_bounds__(256) void bprep_kernel(
    const float* __restrict__ W, const float* __restrict__ means)
{
    int gidx = blockIdx.x;         // 8*352
    int g = gidx / 352, n = gidx % 352;
    int f = threadIdx.x;
    float val;
    if (n < 32) {
        int o = g * 32 + n;
        val = W[f * FDIM + o];
    } else {
        int mat = (n - 32) >> 5;
        int o = g * 32 + ((n - 32) & 31);
        int k = mat >> 1;
        float w = W[f * FDIM + o];
        if ((mat & 1) == 0) val = means[k * FDIM + f] * w;
        else                val = (1.0f / g_ivar[k * FDIM + f]) * w * w;
    }
    g_B[g][n * FDIM + f] = __float2half_rn(val);
}

// ---------------- mma.sync GEMM + epilogue ----------------
__device__ __forceinline__ float ex_relu(float mu, float s) {
    if (s <= 0.0f) return fmaxf(mu, 0.0f);
    float rs = rsqrtf(s);
    float w  = mu * rs;
    float ss = s * rs;               // = sqrt(s)
    return ss * (0.3989422804014327f * __expf(-0.5f * w * w)
                 + 0.5f * w * (1.0f + erff(w * 0.7071067811865476f)));
}

// SMEM layout (per buffer), 80-byte row pitch (conflict-free ldmatrix)
#define OFF_A0H 0
#define OFF_A0L 5120
#define OFF_AMH 10240
#define OFF_B   15360
#define BUFSZ   43520
#define SM_TOTAL (2 * BUFSZ)      // 87040

__device__ __forceinline__ void load_chunk(uint32_t sbuf, int nb, int g, int kc) {
    int t = threadIdx.x;
    const char* srcA0 = (const char*)g_S0h;
    const char* srcA1 = (const char*)g_S0l;
    const char* srcA2 = (const char*)g_SMh;
#pragma unroll
    for (int j = 0; j < 3; j++) {
        int id = t + j * 256;                 // 768 total
        int tile = id >> 8, rem = id & 255;
        int row = rem >> 2, c16 = rem & 3;
        int node = nb + row; if (node >= NNODES) node = NNODES - 1;
        const char* base = tile == 0 ? srcA0 : (tile == 1 ? srcA1 : srcA2);
        const char* src = base + ((size_t)node * FDIM + kc * 32 + c16 * 8) * 2;
        uint32_t dst = sbuf + OFF_A0H + tile * 5120 + row * 80 + c16 * 16;
        cpasync16(dst, src);
    }
    const char* bp = (const char*)&g_B[g][0];
#pragma unroll
    for (int j = 0; j < 6; j++) {
        int id = t + j * 256;                 // 1408 total
        if (id < 1408) {
            int row = id >> 2, c16 = id & 3;
            const char* src = bp + ((size_t)row * FDIM + kc * 32 + c16 * 8) * 2;
            uint32_t dst = sbuf + OFF_B + row * 80 + c16 * 16;
            cpasync16(dst, src);
        }
    }
}

__global__ __launch_bounds__(256, 2) void gemm_mma_kernel(
    const float* __restrict__ bias, float* __restrict__ out)
{
    extern __shared__ char smem[];
    uint32_t sb = smem_u32(smem);
    int t = threadIdx.x;
    int lane = t & 31, wid = t >> 5;
    int wm = wid & 3, wn = wid >> 2;          // 4 m-tiles x 2 n-tiles
    int nb = blockIdx.y * 64;                 // node tile
    int g  = blockIdx.x;                      // group — A reuse in-wave
    int ob = g * 32;

    float acc[11][8];
#pragma unroll
    for (int a = 0; a < 11; a++)
#pragma unroll
        for (int d = 0; d < 8; d++) acc[a][d] = 0.0f;

    load_chunk(sb, nb, g, 0);
    CP_COMMIT();

    int arow = wm * 16 + (lane & 15);
    int acolsel = (lane >> 4) << 3;
    int brow = wn * 16 + (lane & 7) + ((lane >> 4) << 3);
    int bcolsel = ((lane >> 3) & 1) << 3;

    for (int c = 0; c < 8; c++) {
        if (c < 7) { load_chunk(sb + ((c + 1) & 1) * BUFSZ, nb, g, c + 1); CP_COMMIT(); CP_WAIT1(); }
        else CP_WAIT0();
        __syncthreads();

        uint32_t b32 = sb + (c & 1) * BUFSZ;
#pragma unroll
        for (int j = 0; j < 2; j++) {
            uint32_t aoff = (uint32_t)(arow * 80 + (j * 16 + acolsel) * 2);
            uint32_t aH[4], aL[4], aM[4];
            ldsm4(aH, b32 + OFF_A0H + aoff);
            ldsm4(aL, b32 + OFF_A0L + aoff);
            ldsm4(aM, b32 + OFF_AMH + aoff);

            uint32_t boff0 = (uint32_t)(brow * 80 + (j * 16 + bcolsel) * 2);
            uint32_t bq[4];
            // t0 path: (S0h + S0l) * B
            ldsm4(bq, b32 + OFF_B + boff0);
            mma16816(&acc[0][0], aH, &bq[0]); mma16816(&acc[0][4], aH, &bq[2]);
            mma16816(&acc[0][0], aL, &bq[0]); mma16816(&acc[0][4], aL, &bq[2]);
            // SM path: counts * B  (counts exact in fp16)
#pragma unroll
            for (int a = 1; a <= 10; a++) {
                uint32_t boff = boff0 + (uint32_t)(a * 32 * 80);
                ldsm4(bq, b32 + OFF_B + boff);
                mma16816(&acc[a][0], aM, &bq[0]); mma16816(&acc[a][4], aM, &bq[2]);
            }
        }
        __syncthreads();
    }

    int r0 = lane >> 2, c0 = (lane & 3) * 2;
#pragma unroll
    for (int i = 0; i < 2; i++) {
        int node = nb + wm * 16 + r0 + i * 8;
        if (node >= NNODES) continue;
        float deg1 = 1.0f + g_indeg[node];
        float gam[KMIX];
#pragma unroll
        for (int k = 0; k < KMIX; k++) gam[k] = g_gamma[node * KMIX + k];
#pragma unroll
        for (int f = 0; f < 2; f++) {
            int o = ob + wn * 16 + f * 8 + c0;
            float bb0 = bias[o] * deg1;
            float bb1 = bias[o + 1] * deg1;
            int d = f * 4 + i * 2;
            float mu0 = acc[0][d], mu1 = acc[0][d + 1];
            float s0 = 0.f, s1 = 0.f;
#pragma unroll
            for (int k = 0; k < KMIX; k++) {
                s0 += gam[k] * ex_relu(mu0 + acc[1 + 2 * k][d] + bb0,     acc[2 + 2 * k][d]);
                s1 += gam[k] * ex_relu(mu1 + acc[1 + 2 * k][d + 1] + bb1, acc[2 + 2 * k][d + 1]);
            }
            *(float2*)&out[(size_t)node * FDIM + o] = make_float2(s0, s1);
        }
    }
}

// ---------------- launcher ----------------
extern "C" void kernel_launch(void* const* d_in, const int* in_sizes, int n_in,
                              void* d_out, int out_size) {
    const float* x       = (const float*)d_in[0];
    const void*  edges   = d_in[1];
    const void*  mask    = d_in[2];
    const float* logp    = (const float*)d_in[3];
    const float* means   = (const float*)d_in[4];
    const float* logvars = (const float*)d_in[5];
    const float* W       = (const float*)d_in[6];
    const float* bias    = (const float*)d_in[7];
    float* out = (float*)d_out;

    int E = in_sizes[1] / 2;

    cudaFuncSetAttribute(gemm_mma_kernel, cudaFuncAttributeMaxDynamicSharedMemorySize, SM_TOTAL);

    detect_kernel<<<1, 256>>>(mask, edges);
    zero_kernel<<<(NNODES + 255) / 256, 256>>>();
    ivar_kernel<<<(KMIX * FDIM + 255) / 256, 256>>>(logvars);
    prep_kernel<<<NNODES, 256>>>(x, mask, logp, means);

    int eb = (E + 255) / 256;
    count_kernel<<<eb, 256>>>(edges, E);
    scan_kernel<<<1, 1024>>>();
    scatter_kernel<<<eb, 256>>>(edges, E);
    aggregate_kernel<<<NNODES, 256>>>(x);

    bprep_kernel<<<8 * 352, 256>>>(W, means);

    dim3 ggrid(8, (NNODES + 63) / 64);
    gemm_mma_kernel<<<ggrid, 256, SM_TOTAL>>>(bias, out);
}

// round 9
// speedup vs baseline: 1.5243x; 1.5243x over previous
#include <cuda_runtime.h>
#include <cuda_fp16.h>
#include <cstdint>

#define NNODES 50000
#define FDIM   256
#define KMIX   5
#define EMAX   1700000

// ---------------- scratch ----------------
__device__ unsigned g_mbits[NNODES * 8];      // bit mask, 256 bits/node
__device__ float g_indeg[NNODES];
__device__ float g_gamma[NNODES * KMIX];
__device__ int   g_flags[2];
__device__ int   g_count[NNODES];
__device__ int   g_cursor[NNODES];
__device__ int   g_offset[NNODES + 1];
__device__ int   g_sorted[EMAX];
__device__ float g_ivar[KMIX * FDIM];         // exp(-logvars), precomputed once
__device__ float2 g_htab[1025];               // h(w) lookup: value, delta-per-interval
__device__ __half g_S0h[NNODES * FDIM];       // fp16 hi of aggregated S0
__device__ __half g_S0l[NNODES * FDIM];       // fp16 lo residual
__device__ __half g_SMh[NNODES * FDIM];       // aggregated mask counts (exact fp16)
// B concat (single fp16): [group g (32 outs)][352 rows (n)][256 (k)]
__device__ __half g_B[8][352 * 256];

// ---------------- PTX helpers (baseline ISA only) ----------------
__device__ __forceinline__ uint32_t smem_u32(const void* p) {
    uint32_t a;
    asm("{ .reg .u64 t; cvta.to.shared.u64 t, %1; cvt.u32.u64 %0, t; }" : "=r"(a) : "l"(p));
    return a;
}
__device__ __forceinline__ void cpasync16(uint32_t dst, const void* src) {
    asm volatile("cp.async.cg.shared.global [%0], [%1], 16;" :: "r"(dst), "l"(src));
}
#define CP_COMMIT() asm volatile("cp.async.commit_group;" ::: "memory")
#define CP_WAIT1()  asm volatile("cp.async.wait_group 1;" ::: "memory")
#define CP_WAIT0()  asm volatile("cp.async.wait_group 0;" ::: "memory")

__device__ __forceinline__ void ldsm4(uint32_t* r, uint32_t addr) {
    asm volatile("ldmatrix.sync.aligned.m8n8.x4.shared.b16 {%0,%1,%2,%3}, [%4];"
                 : "=r"(r[0]), "=r"(r[1]), "=r"(r[2]), "=r"(r[3]) : "r"(addr));
}
__device__ __forceinline__ void mma16816(float* d, const uint32_t* a, const uint32_t* b) {
    asm volatile("mma.sync.aligned.m16n8k16.row.col.f32.f16.f16.f32 "
                 "{%0,%1,%2,%3}, {%4,%5,%6,%7}, {%8,%9}, {%0,%1,%2,%3};"
                 : "+f"(d[0]), "+f"(d[1]), "+f"(d[2]), "+f"(d[3])
                 : "r"(a[0]), "r"(a[1]), "r"(a[2]), "r"(a[3]), "r"(b[0]), "r"(b[1]));
}

// ---------------- dtype detection + zero counters ----------------
__global__ void detect_kernel(const void* mask, const void* edges) {
    int t = threadIdx.x;
    int any_m = 0, any_e = 0;
    const unsigned char* mb = (const unsigned char*)mask;
    const int* ei = (const int*)edges;
    for (int i = t; i < 4096; i += 256) {
        if (mb[4 * i + 1] != 0) any_m = 1;
        if (ei[2 * i + 1] != 0) any_e = 1;
    }
    any_m = __syncthreads_or(any_m);
    any_e = __syncthreads_or(any_e);
    if (t == 0) { g_flags[0] = any_m ? 1 : 0; g_flags[1] = any_e ? 0 : 1; }
}

__global__ void zero_kernel() {
    int i = blockIdx.x * blockDim.x + threadIdx.x;
    if (i < NNODES) { g_count[i] = 0; g_cursor[i] = 0; }
}

// ---------------- ivar + h-table precompute ----------------
__global__ void ivar_kernel(const float* __restrict__ logvars) {
    int i = blockIdx.x * blockDim.x + threadIdx.x;
    if (i < KMIX * FDIM) g_ivar[i] = expf(-logvars[i]);
}

__device__ __forceinline__ float h_exact(float w) {
    return 0.3989422804014327f * expf(-0.5f * w * w)
         + 0.5f * w * (1.0f + erff(w * 0.7071067811865476f));
}
__global__ void htab_kernel() {
    int i = blockIdx.x * blockDim.x + threadIdx.x;
    if (i > 1024) return;
    float w0 = -8.0f + i * (1.0f / 64.0f);
    float h0 = h_exact(w0);
    float h1 = h_exact(w0 + (1.0f / 64.0f));
    g_htab[i] = make_float2(h0, h1 - h0);     // delta per interval (frac in [0,1))
}

// ---------------- prep: mbits + gamma ----------------
__global__ __launch_bounds__(256) void prep_kernel(
    const float* __restrict__ x, const void* __restrict__ mask,
    const float* __restrict__ logp, const float* __restrict__ means)
{
    int n = blockIdx.x;
    int f = threadIdx.x;
    int idx = n * FDIM + f;
    int m = g_flags[0] ? (int)((const unsigned char*)mask)[idx]
                       : ((const int*)mask)[idx];
    float xv = x[idx];

    unsigned bal = __ballot_sync(0xffffffffu, m);
    int w = f >> 5, lane = f & 31;
    if (lane == 0) g_mbits[n * 8 + w] = bal;

    float q[KMIX];
#pragma unroll
    for (int k = 0; k < KMIX; k++) {
        float d = xv - means[k * FDIM + f];
        float iv = g_ivar[k * FDIM + f];
        q[k] = m ? 0.0f : d * d * iv;
    }
#pragma unroll
    for (int k = 0; k < KMIX; k++)
        for (int off = 16; off; off >>= 1)
            q[k] += __shfl_down_sync(0xffffffffu, q[k], off);

    __shared__ float red[8][KMIX];
    if (lane == 0)
#pragma unroll
        for (int k = 0; k < KMIX; k++) red[w][k] = q[k];
    __syncthreads();
    if (f == 0) {
        float l[KMIX], mx = -1e30f;
#pragma unroll
        for (int k = 0; k < KMIX; k++) {
            float s = 0.f;
            for (int ww = 0; ww < 8; ww++) s += red[ww][k];
            l[k] = logp[k] - 0.5f * s;
            mx = fmaxf(mx, l[k]);
        }
        float e[KMIX], se = 0.f;
#pragma unroll
        for (int k = 0; k < KMIX; k++) { e[k] = __expf(l[k] - mx); se += e[k]; }
        float inv = 1.0f / se;
#pragma unroll
        for (int k = 0; k < KMIX; k++) g_gamma[n * KMIX + k] = e[k] * inv;
    }
}

// ---------------- CSR build ----------------
__global__ void count_kernel(const void* __restrict__ edges, int E) {
    int i = blockIdx.x * blockDim.x + threadIdx.x;
    if (i >= E) return;
    int dst = g_flags[1] ? (int)((const long long*)edges)[E + i]
                         : ((const int*)edges)[E + i];
    atomicAdd(&g_count[dst], 1);
}

__global__ __launch_bounds__(1024) void scan_kernel() {
    const int SEG = (NNODES + 1023) / 1024;
    int t = threadIdx.x;
    int base = t * SEG;
    int s = 0;
    for (int i = 0; i < SEG; i++) {
        int idx = base + i;
        if (idx < NNODES) s += g_count[idx];
    }
    __shared__ int ss[1024];
    ss[t] = s;
    __syncthreads();
    for (int off = 1; off < 1024; off <<= 1) {
        int v = (t >= off) ? ss[t - off] : 0;
        __syncthreads();
        ss[t] += v;
        __syncthreads();
    }
    int run = ss[t] - s;
    for (int i = 0; i < SEG; i++) {
        int idx = base + i;
        if (idx < NNODES) { g_offset[idx] = run; run += g_count[idx]; }
    }
    if (t == 1023) g_offset[NNODES] = ss[1023];
}

__global__ void scatter_kernel(const void* __restrict__ edges, int E) {
    int i = blockIdx.x * blockDim.x + threadIdx.x;
    if (i >= E) return;
    int src, dst;
    if (g_flags[1]) {
        const long long* e = (const long long*)edges;
        src = (int)e[i]; dst = (int)e[E + i];
    } else {
        const int* e = (const int*)edges;
        src = e[i]; dst = e[E + i];
    }
    int pos = atomicAdd(&g_cursor[dst], 1);
    g_sorted[g_offset[dst] + pos] = src;
}

// ---------------- aggregate: CSR gather -> S0h/S0l/SMh + indeg ----------
__global__ __launch_bounds__(256) void aggregate_kernel(const float* __restrict__ x) {
    int n = blockIdx.x;
    int f = threadIdx.x;
    int wsel = f >> 5, bsel = f & 31;

    int beg = g_offset[n], end = g_offset[n + 1];

    unsigned mb = g_mbits[n * 8 + wsel];
    int bit = (mb >> bsel) & 1;
    float xv = __ldg(&x[(size_t)n * FDIM + f]);
    float accS = bit ? 0.0f : xv;
    int cnt = bit;

    __shared__ int ssrc[256];
    for (int chunk = beg; chunk < end; chunk += 256) {
        int nload = min(256, end - chunk);
        __syncthreads();
        if (f < nload) ssrc[f] = g_sorted[chunk + f];
        __syncthreads();
        int i = 0;
        for (; i + 2 <= nload; i += 2) {
            int s0 = ssrc[i], s1 = ssrc[i + 1];
            unsigned m0 = __ldg(&g_mbits[s0 * 8 + wsel]);
            unsigned m1 = __ldg(&g_mbits[s1 * 8 + wsel]);
            float v0 = __ldg(&x[(size_t)s0 * FDIM + f]);
            float v1 = __ldg(&x[(size_t)s1 * FDIM + f]);
            int b0 = (m0 >> bsel) & 1, b1 = (m1 >> bsel) & 1;
            accS += b0 ? 0.0f : v0;
            accS += b1 ? 0.0f : v1;
            cnt += b0 + b1;
        }
        if (i < nload) {
            int s0 = ssrc[i];
            unsigned m0 = __ldg(&g_mbits[s0 * 8 + wsel]);
            float v0 = __ldg(&x[(size_t)s0 * FDIM + f]);
            int b0 = (m0 >> bsel) & 1;
            accS += b0 ? 0.0f : v0;
            cnt += b0;
        }
    }

    int idx = n * FDIM + f;
    __half h = __float2half_rn(accS);
    g_S0h[idx] = h;
    g_S0l[idx] = __float2half_rn(accS - __half2float(h));
    g_SMh[idx] = __float2half_rn((float)cnt);
    if (f == 0) g_indeg[n] = (float)(end - beg);
}

// ---------------- B precompute (n-concat, single fp16) ----------------
__global__ __launch_bounds__(256) void bprep_kernel(
    const float* __restrict__ W, const float* __restrict__ means,
    const float* __restrict__ logvars)
{
    int gidx = blockIdx.x;         // 8*352
    int g = gidx / 352, n = gidx % 352;
    int f = threadIdx.x;
    float val;
    if (n < 32) {
        int o = g * 32 + n;
        val = W[f * FDIM + o];
    } else {
        int mat = (n - 32) >> 5;
        int o = g * 32 + ((n - 32) & 31);
        int k = mat >> 1;
        float w = W[f * FDIM + o];
        if ((mat & 1) == 0) val = means[k * FDIM + f] * w;
        else                val = expf(logvars[k * FDIM + f]) * w * w;
    }
    g_B[g][n * FDIM + f] = __float2half_rn(val);
}

// ---------------- mma.sync GEMM + table epilogue ----------------
__device__ __forceinline__ float ex_relu_tab(float mu, float s, const float2* htab) {
    if (s <= 0.0f) return fmaxf(mu, 0.0f);
    float rs = rsqrtf(s);
    float w  = mu * rs;
    if (w >= 8.0f) return mu;
    if (w <= -8.0f) return 0.0f;
    float ss = s * rs;               // = sqrt(s)
    float p = (w + 8.0f) * 64.0f;
    int i = (int)p;
    float frac = p - (float)i;
    float2 e = htab[i];
    return ss * fmaf(frac, e.y, e.x);
}

// SMEM layout (per buffer), 80-byte row pitch (conflict-free ldmatrix)
#define OFF_A0H 0
#define OFF_A0L 5120
#define OFF_AMH 10240
#define OFF_B   15360
#define BUFSZ   43520
#define OFF_HTAB (2 * BUFSZ)              // 87040
#define SM_TOTAL (2 * BUFSZ + 8224)       // 95264

__device__ __forceinline__ void load_chunk(uint32_t sbuf, int nb, int g, int kc) {
    int t = threadIdx.x;
    const char* srcA0 = (const char*)g_S0h;
    const char* srcA1 = (const char*)g_S0l;
    const char* srcA2 = (const char*)g_SMh;
#pragma unroll
    for (int j = 0; j < 3; j++) {
        int id = t + j * 256;                 // 768 total
        int tile = id >> 8, rem = id & 255;
        int row = rem >> 2, c16 = rem & 3;
        int node = nb + row; if (node >= NNODES) node = NNODES - 1;
        const char* base = tile == 0 ? srcA0 : (tile == 1 ? srcA1 : srcA2);
        const char* src = base + ((size_t)node * FDIM + kc * 32 + c16 * 8) * 2;
        uint32_t dst = sbuf + OFF_A0H + tile * 5120 + row * 80 + c16 * 16;
        cpasync16(dst, src);
    }
    const char* bp = (const char*)&g_B[g][0];
#pragma unroll
    for (int j = 0; j < 6; j++) {
        int id = t + j * 256;                 // 1408 total
        if (id < 1408) {
            int row = id >> 2, c16 = id & 3;
            const char* src = bp + ((size_t)row * FDIM + kc * 32 + c16 * 8) * 2;
            uint32_t dst = sbuf + OFF_B + row * 80 + c16 * 16;
            cpasync16(dst, src);
        }
    }
}

__global__ __launch_bounds__(256, 2) void gemm_mma_kernel(
    const float* __restrict__ bias, float* __restrict__ out)
{
    extern __shared__ char smem[];
    uint32_t sb = smem_u32(smem);
    int t = threadIdx.x;
    int lane = t & 31, wid = t >> 5;
    int wm = wid & 3, wn = wid >> 2;          // 4 m-tiles x 2 n-tiles
    int nb = blockIdx.y * 64;                 // node tile
    int g  = blockIdx.x;                      // group — A reuse in-wave
    int ob = g * 32;

    // copy h-table into smem (ordered by the first __syncthreads below)
    float2* htab = (float2*)(smem + OFF_HTAB);
    for (int i = t; i < 1025; i += 256) htab[i] = g_htab[i];

    float acc[11][8];
#pragma unroll
    for (int a = 0; a < 11; a++)
#pragma unroll
        for (int d = 0; d < 8; d++) acc[a][d] = 0.0f;

    load_chunk(sb, nb, g, 0);
    CP_COMMIT();

    int arow = wm * 16 + (lane & 15);
    int acolsel = (lane >> 4) << 3;
    int brow = wn * 16 + (lane & 7) + ((lane >> 4) << 3);
    int bcolsel = ((lane >> 3) & 1) << 3;

    for (int c = 0; c < 8; c++) {
        if (c < 7) { load_chunk(sb + ((c + 1) & 1) * BUFSZ, nb, g, c + 1); CP_COMMIT(); CP_WAIT1(); }
        else CP_WAIT0();
        __syncthreads();

        uint32_t b32 = sb + (c & 1) * BUFSZ;
#pragma unroll
        for (int j = 0; j < 2; j++) {
            uint32_t aoff = (uint32_t)(arow * 80 + (j * 16 + acolsel) * 2);
            uint32_t aH[4], aL[4], aM[4];
            ldsm4(aH, b32 + OFF_A0H + aoff);
            ldsm4(aL, b32 + OFF_A0L + aoff);
            ldsm4(aM, b32 + OFF_AMH + aoff);

            uint32_t boff0 = (uint32_t)(brow * 80 + (j * 16 + bcolsel) * 2);
            uint32_t bq[4];
            // t0 path: (S0h + S0l) * B
            ldsm4(bq, b32 + OFF_B + boff0);
            mma16816(&acc[0][0], aH, &bq[0]); mma16816(&acc[0][4], aH, &bq[2]);
            mma16816(&acc[0][0], aL, &bq[0]); mma16816(&acc[0][4], aL, &bq[2]);
            // SM path: counts * B  (counts exact in fp16)
#pragma unroll
            for (int a = 1; a <= 10; a++) {
                uint32_t boff = boff0 + (uint32_t)(a * 32 * 80);
                ldsm4(bq, b32 + OFF_B + boff);
                mma16816(&acc[a][0], aM, &bq[0]); mma16816(&acc[a][4], aM, &bq[2]);
            }
        }
        __syncthreads();
    }

    int r0 = lane >> 2, c0 = (lane & 3) * 2;
#pragma unroll
    for (int i = 0; i < 2; i++) {
        int node = nb + wm * 16 + r0 + i * 8;
        if (node >= NNODES) continue;
        float deg1 = 1.0f + g_indeg[node];
        float gam[KMIX];
#pragma unroll
        for (int k = 0; k < KMIX; k++) gam[k] = g_gamma[node * KMIX + k];
#pragma unroll
        for (int f = 0; f < 2; f++) {
            int o = ob + wn * 16 + f * 8 + c0;
            float bb0 = bias[o] * deg1;
            float bb1 = bias[o + 1] * deg1;
            int d = f * 4 + i * 2;
            float mu0 = acc[0][d], mu1 = acc[0][d + 1];
            float s0 = 0.f, s1 = 0.f;
#pragma unroll
            for (int k = 0; k < KMIX; k++) {
                s0 += gam[k] * ex_relu_tab(mu0 + acc[1 + 2 * k][d] + bb0,     acc[2 + 2 * k][d],     htab);
                s1 += gam[k] * ex_relu_tab(mu1 + acc[1 + 2 * k][d + 1] + bb1, acc[2 + 2 * k][d + 1], htab);
            }
            *(float2*)&out[(size_t)node * FDIM + o] = make_float2(s0, s1);
        }
    }
}

// ---------------- launcher ----------------
extern "C" void kernel_launch(void* const* d_in, const int* in_sizes, int n_in,
                              void* d_out, int out_size) {
    const float* x       = (const float*)d_in[0];
    const void*  edges   = d_in[1];
    const void*  mask    = d_in[2];
    const float* logp    = (const float*)d_in[3];
    const float* means   = (const float*)d_in[4];
    const float* logvars = (const float*)d_in[5];
    const float* W       = (const float*)d_in[6];
    const float* bias    = (const float*)d_in[7];
    float* out = (float*)d_out;

    int E = in_sizes[1] / 2;

    cudaFuncSetAttribute(gemm_mma_kernel, cudaFuncAttributeMaxDynamicSharedMemorySize, SM_TOTAL);

    detect_kernel<<<1, 256>>>(mask, edges);
    zero_kernel<<<(NNODES + 255) / 256, 256>>>();
    ivar_kernel<<<(KMIX * FDIM + 255) / 256, 256>>>(logvars);
    htab_kernel<<<5, 256>>>();
    prep_kernel<<<NNODES, 256>>>(x, mask, logp, means);

    int eb = (E + 255) / 256;
    count_kernel<<<eb, 256>>>(edges, E);
    scan_kernel<<<1, 1024>>>();
    scatter_kernel<<<eb, 256>>>(edges, E);
    aggregate_kernel<<<NNODES, 256>>>(x);

    bprep_kernel<<<8 * 352, 256>>>(W, means, logvars);

    dim3 ggrid(8, (NNODES + 63) / 64);
    gemm_mma_kernel<<<ggrid, 256, SM_TOTAL>>>(bias, out);
}